// round 1
// baseline (speedup 1.0000x reference)
#include <cuda_runtime.h>
#include <math.h>

// Spectral_Pool: out[b,m1,m2,c] = Re( Ac @ X[b,:,:,c] @ Ac^T )
//   Ac[m,n] = (1/217) * e^{2*pi*i*n/256} * sin(217*pi*a)/sin(pi*a),  a = m/217 - n/256
// Split Ac = P + iQ  ->  out = P X P^T - Q X Q^T  (two real batched GEMM stages).
//
// Stage 1: per (b,w):  T[mm,c] = sum_h At1[h][mm] * X[b,h,w,c]   (mm: P rows 0..216, Q rows 224..440)
// Stage 2: per (b,m1): out[m2,c] = sum_{k<512} At2[k][m2] * Trow(k)[c]
//   where k<256 -> Trow = T[b,w=k,mm=m1],  k>=256 -> Trow = T[b,w=k-256,mm=224+m1]
//   and At2[k][m2] = P[m2][k] (k<256) or -Q[m2][k-256].

#define BATCH 16
#define HDIM  256
#define CDIM  64
#define KOUT  217
#define MPAD  224
#define TROWS 448
#define K2    512
#define KT    16

// ---- device globals (no cudaMalloc allowed) ----
__device__ float g_At1[HDIM * TROWS];                       // [n][mm]   458 KB
__device__ float g_At2[K2 * MPAD];                          // [k][m2]   458 KB
__device__ float g_T[(size_t)BATCH * HDIM * TROWS * CDIM];  // [b][w][mm][c]  ~470 MB

// ------------------------------------------------------------------
// Init: build P/Q matrices (double precision closed form, exact math)
// ------------------------------------------------------------------
__device__ __forceinline__ double dirichlet_d(long long p) {
    // d = sin(217*pi*a)/sin(pi*a) with a = p/55552 ; p = 256*m - 217*n
    const double PI = 3.14159265358979323846;
    if (p == 0) return 217.0;
    return sin(PI * (double)p / 256.0) / sin(PI * (double)p / 55552.0);
}

__global__ void init_mats() {
    const double PI = 3.14159265358979323846;
    int idx = blockIdx.x * blockDim.x + threadIdx.x;

    if (idx < HDIM * TROWS) {               // g_At1[n][mm]
        int n  = idx / TROWS;
        int mm = idx % TROWS;
        float v = 0.f;
        int m = -1; bool isQ = false;
        if (mm < KOUT)                       { m = mm; }
        else if (mm >= MPAD && mm < MPAD+KOUT){ m = mm - MPAD; isQ = true; }
        if (m >= 0) {
            long long p = 256LL * m - 217LL * n;
            double d  = dirichlet_d(p);
            double ph = 2.0 * PI * (double)n / 256.0;
            v = (float)((d / 217.0) * (isQ ? sin(ph) : cos(ph)));
        }
        g_At1[idx] = v;
    }

    int idx2 = idx - HDIM * TROWS;
    if (idx2 >= 0 && idx2 < K2 * MPAD) {    // g_At2[k][m2]
        int k  = idx2 / MPAD;
        int m2 = idx2 % MPAD;
        float v = 0.f;
        if (m2 < KOUT) {
            int n = k & 255;
            bool isQ = (k >= 256);
            long long p = 256LL * m2 - 217LL * n;
            double d  = dirichlet_d(p);
            double ph = 2.0 * PI * (double)n / 256.0;
            v = (float)((d / 217.0) * (isQ ? -sin(ph) : cos(ph)));
        }
        g_At2[idx2] = v;
    }
}

// ------------------------------------------------------------------
// Stage 1: T[b][w][mm][c] = sum_h At1[h][mm] * X[b][h][w][c]
// grid (w=256, b=16, mtile=2), 224 threads, 8x8 microtile
// ------------------------------------------------------------------
__global__ __launch_bounds__(224, 2)
void stage1(const float* __restrict__ X) {
    __shared__ float Asm[KT][MPAD];   // [kk][m]
    __shared__ float Bsm[KT][CDIM];   // [kk][c]

    const int w = blockIdx.x, b = blockIdx.y;
    const int mbase = blockIdx.z * MPAD;      // 0 or 224
    const int tid = threadIdx.x;
    const int tm = tid >> 3;                  // 0..27
    const int tc = tid & 7;                   // 0..7

    float acc[8][8];
#pragma unroll
    for (int i = 0; i < 8; i++)
#pragma unroll
        for (int j = 0; j < 8; j++) acc[i][j] = 0.f;

    const float* xcol = X + (size_t)b * HDIM * HDIM * CDIM + (size_t)w * CDIM;

    for (int k0 = 0; k0 < HDIM; k0 += KT) {
        // load B tile: KT rows of 64 contiguous floats (row stride 16384 floats)
        {
            int i = tid;
            if (i < KT * CDIM / 4) {
                int kk = i >> 4, c4 = i & 15;
                float4 v = *(const float4*)(xcol + (size_t)(k0 + kk) * (HDIM * CDIM) + c4 * 4);
                *(float4*)&Bsm[kk][c4 * 4] = v;
            }
            i += 224;
            if (i < KT * CDIM / 4) {
                int kk = i >> 4, c4 = i & 15;
                float4 v = *(const float4*)(xcol + (size_t)(k0 + kk) * (HDIM * CDIM) + c4 * 4);
                *(float4*)&Bsm[kk][c4 * 4] = v;
            }
        }
        // load A tile: At1 rows k0..k0+15, cols mbase..mbase+223 (row stride 448)
#pragma unroll
        for (int j = 0; j < 4; j++) {
            int i = tid + j * 224;            // 0..895
            int kk = i / 56, m4 = i % 56;
            float4 v = *(const float4*)(g_At1 + (size_t)(k0 + kk) * TROWS + mbase + m4 * 4);
            *(float4*)&Asm[kk][m4 * 4] = v;
        }
        __syncthreads();

#pragma unroll 4
        for (int kk = 0; kk < KT; kk++) {
            float4 a0 = *(const float4*)&Asm[kk][tm * 8];
            float4 a1 = *(const float4*)&Asm[kk][tm * 8 + 4];
            float4 b0 = *(const float4*)&Bsm[kk][tc * 8];
            float4 b1 = *(const float4*)&Bsm[kk][tc * 8 + 4];
            float a[8] = {a0.x, a0.y, a0.z, a0.w, a1.x, a1.y, a1.z, a1.w};
            float bb[8] = {b0.x, b0.y, b0.z, b0.w, b1.x, b1.y, b1.z, b1.w};
#pragma unroll
            for (int i = 0; i < 8; i++)
#pragma unroll
                for (int j = 0; j < 8; j++) acc[i][j] += a[i] * bb[j];
        }
        __syncthreads();
    }

    // store T
    float* tb = g_T + ((size_t)(b * HDIM + w)) * TROWS * CDIM;
#pragma unroll
    for (int i = 0; i < 8; i++) {
        int mm = mbase + tm * 8 + i;
        float* dst = tb + (size_t)mm * CDIM + tc * 8;
        *(float4*)dst       = make_float4(acc[i][0], acc[i][1], acc[i][2], acc[i][3]);
        *(float4*)(dst + 4) = make_float4(acc[i][4], acc[i][5], acc[i][6], acc[i][7]);
    }
}

// ------------------------------------------------------------------
// Stage 2: out[b][m1][m2][c] = sum_k At2[k][m2] * Trow(b,m1,k)[c]
// grid (m1=217, b=16), 224 threads, 8x8 microtile, M=224 (m2), K=512
// ------------------------------------------------------------------
__global__ __launch_bounds__(224, 2)
void stage2(float* __restrict__ out) {
    __shared__ float Asm[KT][MPAD];
    __shared__ float Bsm[KT][CDIM];

    const int m1 = blockIdx.x, b = blockIdx.y;
    const int tid = threadIdx.x;
    const int tm = tid >> 3;
    const int tc = tid & 7;

    float acc[8][8];
#pragma unroll
    for (int i = 0; i < 8; i++)
#pragma unroll
        for (int j = 0; j < 8; j++) acc[i][j] = 0.f;

    for (int k0 = 0; k0 < K2; k0 += KT) {
        // load B tile: row k -> T[b][w = k&255][mm = (k<256)? m1 : 224+m1][c]
        {
            int i = tid;
            if (i < KT * CDIM / 4) {
                int kk = i >> 4, c4 = i & 15;
                int k = k0 + kk;
                int wv = k & 255;
                int mm = (k < 256) ? m1 : (MPAD + m1);
                float4 v = *(const float4*)(g_T + ((size_t)(b * HDIM + wv) * TROWS + mm) * CDIM + c4 * 4);
                *(float4*)&Bsm[kk][c4 * 4] = v;
            }
            i += 224;
            if (i < KT * CDIM / 4) {
                int kk = i >> 4, c4 = i & 15;
                int k = k0 + kk;
                int wv = k & 255;
                int mm = (k < 256) ? m1 : (MPAD + m1);
                float4 v = *(const float4*)(g_T + ((size_t)(b * HDIM + wv) * TROWS + mm) * CDIM + c4 * 4);
                *(float4*)&Bsm[kk][c4 * 4] = v;
            }
        }
        // load A tile: At2 rows k0..k0+15, 224 cols (row stride 224)
#pragma unroll
        for (int j = 0; j < 4; j++) {
            int i = tid + j * 224;
            int kk = i / 56, m4 = i % 56;
            float4 v = *(const float4*)(g_At2 + (size_t)(k0 + kk) * MPAD + m4 * 4);
            *(float4*)&Asm[kk][m4 * 4] = v;
        }
        __syncthreads();

#pragma unroll 4
        for (int kk = 0; kk < KT; kk++) {
            float4 a0 = *(const float4*)&Asm[kk][tm * 8];
            float4 a1 = *(const float4*)&Asm[kk][tm * 8 + 4];
            float4 b0 = *(const float4*)&Bsm[kk][tc * 8];
            float4 b1 = *(const float4*)&Bsm[kk][tc * 8 + 4];
            float a[8] = {a0.x, a0.y, a0.z, a0.w, a1.x, a1.y, a1.z, a1.w};
            float bb[8] = {b0.x, b0.y, b0.z, b0.w, b1.x, b1.y, b1.z, b1.w};
#pragma unroll
            for (int i = 0; i < 8; i++)
#pragma unroll
                for (int j = 0; j < 8; j++) acc[i][j] += a[i] * bb[j];
        }
        __syncthreads();
    }

    // store out[b][m1][m2][c], m2 < 217
    float* ob = out + ((size_t)(b * KOUT + m1)) * KOUT * CDIM;
#pragma unroll
    for (int i = 0; i < 8; i++) {
        int m2 = tm * 8 + i;
        if (m2 < KOUT) {
            float* dst = ob + (size_t)m2 * CDIM + tc * 8;
            *(float4*)dst       = make_float4(acc[i][0], acc[i][1], acc[i][2], acc[i][3]);
            *(float4*)(dst + 4) = make_float4(acc[i][4], acc[i][5], acc[i][6], acc[i][7]);
        }
    }
}

// ------------------------------------------------------------------
extern "C" void kernel_launch(void* const* d_in, const int* in_sizes, int n_in,
                              void* d_out, int out_size) {
    const float* X = (const float*)d_in[0];
    float* out = (float*)d_out;

    const int total = HDIM * TROWS + K2 * MPAD;   // 229376
    init_mats<<<(total + 255) / 256, 256>>>();
    stage1<<<dim3(HDIM, BATCH, 2), 224>>>(X);
    stage2<<<dim3(KOUT, BATCH, 1), 224>>>(out);
}

// round 7
// speedup vs baseline: 2.0905x; 2.0905x over previous
#include <cuda_runtime.h>
#include <math.h>

// Spectral_Pool: out = P X P^T - Q X Q^T  (P+iQ = Dirichlet DFT crop matrix)
// via two bf16 3-split GEMM stages on mma.sync.m16n8k16 (sm_100 legacy tensor path).
//
// Stage1 (per b, w-blk, c-blk, z):  T_z[p, c, w] = sum_h A1_z[p,h] X[b,h,w,c]
//   z=0: A1 = P rows (217, padded 256), z=1: Q rows.  T stored bf16 hi/lo [b][z*224+p][c][w].
// Stage2 (per b, row-pair mi): out[mi, mo, c] = sum_{j,w} A2[mo, j*256+w] T[b, j*224+mi, c, w]
//   A2[mo][j*256+w] = j ? -Q[mo][w] : P[mo][w].

#define PI_D 3.14159265358979323846

// ---------------- device globals ----------------
// fragment-ordered A matrices: [k16][...][mt][hl][lane][8] bf16
__device__ __align__(16) unsigned short g_A1f[16 * 2 * 16 * 2 * 32 * 8];  // 512 KB
__device__ __align__(16) unsigned short g_A2f[32 * 16 * 2 * 32 * 8];      // 512 KB
// T intermediate: [b 16][row 448][c 64][w 256] bf16, hi and lo
__device__ __align__(16) unsigned short g_Th[(size_t)16 * 448 * 64 * 256];
__device__ __align__(16) unsigned short g_Tl[(size_t)16 * 448 * 64 * 256];

// ---------------- helpers ----------------
__device__ __forceinline__ unsigned su32(const void* p) {
    unsigned r;
    asm("{ .reg .u64 t; cvta.to.shared.u64 t, %1; cvt.u32.u64 %0, t; }" : "=r"(r) : "l"(p));
    return r;
}
__device__ __forceinline__ void cp16(unsigned s, const void* g) {
    asm volatile("cp.async.cg.shared.global [%0],[%1],16;" :: "r"(s), "l"(g));
}
__device__ __forceinline__ void cp_commit() { asm volatile("cp.async.commit_group;"); }
__device__ __forceinline__ void cp_wait0() { asm volatile("cp.async.wait_group 0;"); }

__device__ __forceinline__ void mma_bf16(float* d, const unsigned* a, const unsigned* b) {
    asm volatile(
        "mma.sync.aligned.m16n8k16.row.col.f32.bf16.bf16.f32 "
        "{%0,%1,%2,%3},{%4,%5,%6,%7},{%8,%9},{%0,%1,%2,%3};"
        : "+f"(d[0]), "+f"(d[1]), "+f"(d[2]), "+f"(d[3])
        : "r"(a[0]), "r"(a[1]), "r"(a[2]), "r"(a[3]), "r"(b[0]), "r"(b[1]));
}

__device__ __forceinline__ void split2(float f, unsigned short& h, unsigned short& l) {
    unsigned u = __float_as_uint(f);
    unsigned hb = (u + 0x7FFFu + ((u >> 16) & 1u)) >> 16;   // RNE to bf16
    h = (unsigned short)hb;
    float r = f - __uint_as_float(hb << 16);
    unsigned ur = __float_as_uint(r);
    l = (unsigned short)((ur + 0x7FFFu + ((ur >> 16) & 1u)) >> 16);
}

// smem layout (bytes), identical for both stages:
//   A bufs:  [0, 32768), [32768, 65536)
//   B hi:    65536 + buf*20480 ; B lo at +10240.
//   B row stride 80 B (16B-aligned for cp.async; 20-bank stride -> conflict-free), 128 rows.
#define SM_A(buf)  ((buf) * 32768)
#define SM_BH(buf) (65536 + (buf) * 20480)
#define SM_BL(buf) (65536 + (buf) * 20480 + 10240)
#define BROW 80
#define SMEM_SZ 106496

// ---------------- init: build fragment-ordered A1/A2 ----------------
__device__ __forceinline__ double dirichlet_d(long long p) {
    if (p == 0) return 217.0;
    return sin(PI_D * (double)p / 256.0) / sin(PI_D * (double)p / 55552.0);
}

__global__ void init_mats() {
    int t = blockIdx.x * blockDim.x + threadIdx.x;
    if (t >= 32768) return;
    unsigned short hi8[8], lo8[8];

    if (t < 16384) {
        int lane = t & 31, mt = (t >> 5) & 15, zz = (t >> 9) & 1, k16 = t >> 10;
        int gid = lane >> 2, tig = lane & 3;
#pragma unroll
        for (int r = 0; r < 8; r++) {
            int row = gid + ((r >> 1) & 1) * 8;
            int col = tig * 2 + (r & 1) + ((r >> 2) & 1) * 8;
            int ml = mt * 16 + row;
            int h = k16 * 16 + col;
            double v = 0.0;
            if (ml < 217) {
                double d = dirichlet_d(256LL * ml - 217LL * h);
                double ph = 2.0 * PI_D * (double)h / 256.0;
                v = (d / 217.0) * (zz ? sin(ph) : cos(ph));
            }
            split2((float)v, hi8[r], lo8[r]);
        }
        size_t blk = (size_t)(k16 * 2 + zz) * 16 + mt;
        size_t base = blk * 512 + lane * 8;
        *reinterpret_cast<uint4*>(&g_A1f[base]) = *reinterpret_cast<uint4*>(hi8);
        *reinterpret_cast<uint4*>(&g_A1f[base + 256]) = *reinterpret_cast<uint4*>(lo8);
    } else {
        int t2 = t - 16384;
        int lane = t2 & 31, mt = (t2 >> 5) & 15, k16 = t2 >> 9;
        int gid = lane >> 2, tig = lane & 3;
#pragma unroll
        for (int r = 0; r < 8; r++) {
            int row = gid + ((r >> 1) & 1) * 8;
            int col = tig * 2 + (r & 1) + ((r >> 2) & 1) * 8;
            int mo = mt * 16 + row;
            int k = k16 * 16 + col;
            double v = 0.0;
            if (mo < 217) {
                int j = k >> 8, w = k & 255;
                double d = dirichlet_d(256LL * mo - 217LL * w);
                double ph = 2.0 * PI_D * (double)w / 256.0;
                v = (d / 217.0) * (j ? -sin(ph) : cos(ph));
            }
            split2((float)v, hi8[r], lo8[r]);
        }
        size_t blk = (size_t)k16 * 16 + mt;
        size_t base = blk * 512 + lane * 8;
        *reinterpret_cast<uint4*>(&g_A2f[base]) = *reinterpret_cast<uint4*>(hi8);
        *reinterpret_cast<uint4*>(&g_A2f[base + 256]) = *reinterpret_cast<uint4*>(lo8);
    }
}

// ---------------- shared mma chunk (k=32) ----------------
// warp tile M64 x N32; wm = wid&3, wn = wid>>2; acc[4 mt][4 nt][4]
__device__ __forceinline__ void mma_chunk(unsigned char* sm, int buf, int wm, int wn,
                                          int lane, float acc[4][4][4]) {
    int gid = lane >> 2, tig = lane & 3;
#pragma unroll
    for (int kk = 0; kk < 2; kk++) {
        unsigned bh[4][2], bl[4][2];
#pragma unroll
        for (int nt = 0; nt < 4; nt++) {
            int n = wn * 32 + nt * 8 + gid;
            int base = n * BROW + kk * 32 + tig * 4;
            bh[nt][0] = *reinterpret_cast<const unsigned*>(sm + SM_BH(buf) + base);
            bh[nt][1] = *reinterpret_cast<const unsigned*>(sm + SM_BH(buf) + base + 16);
            bl[nt][0] = *reinterpret_cast<const unsigned*>(sm + SM_BL(buf) + base);
            bl[nt][1] = *reinterpret_cast<const unsigned*>(sm + SM_BL(buf) + base + 16);
        }
        unsigned a[4][4];
#pragma unroll
        for (int mt = 0; mt < 4; mt++) {
            const uint4 v = *reinterpret_cast<const uint4*>(
                sm + SM_A(buf) + (((kk * 16 + wm * 4 + mt) * 2 + 0) * 32 + lane) * 16);
            a[mt][0] = v.x; a[mt][1] = v.y; a[mt][2] = v.z; a[mt][3] = v.w;
        }
#pragma unroll
        for (int mt = 0; mt < 4; mt++)
#pragma unroll
            for (int nt = 0; nt < 4; nt++) mma_bf16(acc[mt][nt], a[mt], bh[nt]);
#pragma unroll
        for (int mt = 0; mt < 4; mt++)
#pragma unroll
            for (int nt = 0; nt < 4; nt++) mma_bf16(acc[mt][nt], a[mt], bl[nt]);
#pragma unroll
        for (int mt = 0; mt < 4; mt++) {
            const uint4 v = *reinterpret_cast<const uint4*>(
                sm + SM_A(buf) + (((kk * 16 + wm * 4 + mt) * 2 + 1) * 32 + lane) * 16);
            a[mt][0] = v.x; a[mt][1] = v.y; a[mt][2] = v.z; a[mt][3] = v.w;
        }
#pragma unroll
        for (int mt = 0; mt < 4; mt++)
#pragma unroll
            for (int nt = 0; nt < 4; nt++) mma_bf16(acc[mt][nt], a[mt], bh[nt]);
    }
}

// ---------------- stage 1 ----------------
// grid (32 wblk, 16 b, 8 = cblk*2+z), 512 threads. M=256, N=128 (8w x 16c), K=256.
__global__ __launch_bounds__(512, 1) void stage1(const float* __restrict__ X) {
    extern __shared__ unsigned char sm[];
    const int tid = threadIdx.x, wid = tid >> 5, lane = tid & 31;
    const int wm = wid & 3, wn = wid >> 2;
    const int gid = lane >> 2, tig = lane & 3;
    const int b = blockIdx.y, w0 = blockIdx.x * 8;
    const int zz = blockIdx.z & 1, c0 = (blockIdx.z >> 1) * 16;

    float acc[4][4][4];
#pragma unroll
    for (int i = 0; i < 4; i++)
#pragma unroll
        for (int j = 0; j < 4; j++)
#pragma unroll
            for (int k = 0; k < 4; k++) acc[i][j][k] = 0.f;

    float4 xr[2];
    // prefetch chunk 0
#pragma unroll
    for (int p = 0; p < 2; p++) {
        int i = tid + p * 512;
        int kk = i >> 5, rr = i & 31, wl = rr >> 2, c4 = rr & 3;
        xr[p] = *reinterpret_cast<const float4*>(
            X + ((size_t)((b * 256 + kk) * 256) + (w0 + wl)) * 64 + c0 + c4 * 4);
    }

    for (int ch = 0; ch < 8; ch++) {
        const int buf = ch & 1;
        // B: regs -> smem (split hi/lo), n = (c_local)*8 + wl, k = kk
#pragma unroll
        for (int p = 0; p < 2; p++) {
            int i = tid + p * 512;
            int kk = i >> 5, rr = i & 31, wl = rr >> 2, c4 = rr & 3;
            float v[4] = {xr[p].x, xr[p].y, xr[p].z, xr[p].w};
#pragma unroll
            for (int e = 0; e < 4; e++) {
                unsigned short h, l;
                split2(v[e], h, l);
                int n = (c4 * 4 + e) * 8 + wl;
                *reinterpret_cast<unsigned short*>(sm + SM_BH(buf) + n * BROW + kk * 2) = h;
                *reinterpret_cast<unsigned short*>(sm + SM_BL(buf) + n * BROW + kk * 2) = l;
            }
        }
        // A: cp.async 32KB (two pre-built fragment blocks)
#pragma unroll
        for (int q = 0; q < 4; q++) {
            int i = tid + q * 512;
            int kk2 = i >> 10, o = i & 1023;
            cp16(su32(sm + SM_A(buf) + kk2 * 16384 + o * 16),
                 reinterpret_cast<const char*>(g_A1f) +
                     (size_t)((ch * 2 + kk2) * 2 + zz) * 16384 + o * 16);
        }
        cp_commit();
        // prefetch next chunk X
        if (ch < 7) {
#pragma unroll
            for (int p = 0; p < 2; p++) {
                int i = tid + p * 512;
                int kk = i >> 5, rr = i & 31, wl = rr >> 2, c4 = rr & 3;
                xr[p] = *reinterpret_cast<const float4*>(
                    X + ((size_t)((b * 256 + (ch + 1) * 32 + kk) * 256) + (w0 + wl)) * 64 +
                    c0 + c4 * 4);
            }
        }
        cp_wait0();
        __syncthreads();
        mma_chunk(sm, buf, wm, wn, lane, acc);
        __syncthreads();
    }

    // epilogue: split D -> bf16 hi/lo, T[b][zz*224+row][c][w] (4B packed w-pairs)
#pragma unroll
    for (int mt = 0; mt < 4; mt++) {
#pragma unroll
        for (int nt = 0; nt < 4; nt++) {
            int n0 = wn * 32 + nt * 8 + 2 * tig;
            int w = w0 + (n0 & 7);
            int cc = c0 + (n0 >> 3);
            int lr0 = wm * 64 + mt * 16 + gid;
#pragma unroll
            for (int half = 0; half < 2; half++) {
                int lr = lr0 + half * 8;
                if (lr < 224) {
                    unsigned short h0, l0, h1, l1;
                    split2(acc[mt][nt][half * 2 + 0], h0, l0);
                    split2(acc[mt][nt][half * 2 + 1], h1, l1);
                    size_t elem = ((size_t)((b * 448 + zz * 224 + lr) * 64 + cc)) * 256 + w;
                    *reinterpret_cast<unsigned*>(reinterpret_cast<char*>(g_Th) + elem * 2) =
                        (unsigned)h0 | ((unsigned)h1 << 16);
                    *reinterpret_cast<unsigned*>(reinterpret_cast<char*>(g_Tl) + elem * 2) =
                        (unsigned)l0 | ((unsigned)l1 << 16);
                }
            }
        }
    }
}

// ---------------- stage 2 ----------------
// grid (109 mi-pairs, 16 b), 512 threads. M=256 (mo), N=128 (2 mi x 64 c), K=512.
__device__ __forceinline__ void s2_fill(unsigned char* sm, int buf, int ch, int tid,
                                        int b, int m2t) {
    // A: 32KB
#pragma unroll
    for (int q = 0; q < 4; q++) {
        int i = tid + q * 512;
        int kk2 = i >> 10, o = i & 1023;
        cp16(su32(sm + SM_A(buf) + kk2 * 16384 + o * 16),
             reinterpret_cast<const char*>(g_A2f) + (size_t)(ch * 2 + kk2) * 16384 + o * 16);
    }
    // B: 16KB from T (already bf16 hi/lo, w-contiguous)
    const int j = ch >> 3, w0 = (ch & 7) * 32;
#pragma unroll
    for (int p = 0; p < 2; p++) {
        int i = tid + p * 512;           // 0..1023
        int n = i >> 3, aL = (i >> 2) & 1, qq = i & 3;
        int m2l = n >> 6, cc = n & 63;
        size_t elem = ((size_t)((b * 448 + j * 224 + m2t * 2 + m2l) * 64 + cc)) * 256 + w0;
        const char* src =
            reinterpret_cast<const char*>(aL ? g_Tl : g_Th) + elem * 2 + qq * 16;
        cp16(su32(sm + (aL ? SM_BL(buf) : SM_BH(buf)) + n * BROW + qq * 16), src);
    }
    cp_commit();
}

__global__ __launch_bounds__(512, 1) void stage2(float* __restrict__ out) {
    extern __shared__ unsigned char sm[];
    const int tid = threadIdx.x, wid = tid >> 5, lane = tid & 31;
    const int wm = wid & 3, wn = wid >> 2;
    const int gid = lane >> 2, tig = lane & 3;
    const int b = blockIdx.y, m2t = blockIdx.x;

    float acc[4][4][4];
#pragma unroll
    for (int i = 0; i < 4; i++)
#pragma unroll
        for (int j = 0; j < 4; j++)
#pragma unroll
            for (int k = 0; k < 4; k++) acc[i][j][k] = 0.f;

    s2_fill(sm, 0, 0, tid, b, m2t);
    for (int ch = 0; ch < 16; ch++) {
        cp_wait0();          // fill(ch) complete
        __syncthreads();     // all warps past mma(ch-1): buf^1 safe to overwrite
        if (ch < 15) s2_fill(sm, (ch + 1) & 1, ch + 1, tid, b, m2t);
        mma_chunk(sm, ch & 1, wm, wn, lane, acc);
    }

    // epilogue: out[b][mi][mo][c]
#pragma unroll
    for (int mt = 0; mt < 4; mt++) {
#pragma unroll
        for (int nt = 0; nt < 4; nt++) {
            int n0 = wn * 32 + nt * 8 + 2 * tig;
            int mi = m2t * 2 + (n0 >> 6);
            int cc = n0 & 63;
            int mo0 = wm * 64 + mt * 16 + gid;
            if (mi < 217) {
#pragma unroll
                for (int half = 0; half < 2; half++) {
                    int mo = mo0 + half * 8;
                    if (mo < 217) {
                        size_t e = ((size_t)((b * 217 + mi) * 217 + mo)) * 64 + cc;
                        float2 v = make_float2(acc[mt][nt][half * 2 + 0],
                                               acc[mt][nt][half * 2 + 1]);
                        *reinterpret_cast<float2*>(out + e) = v;
                    }
                }
            }
        }
    }
}

// ---------------- launch ----------------
extern "C" void kernel_launch(void* const* d_in, const int* in_sizes, int n_in,
                              void* d_out, int out_size) {
    const float* X = (const float*)d_in[0];
    float* out = (float*)d_out;

    cudaFuncSetAttribute(stage1, cudaFuncAttributeMaxDynamicSharedMemorySize, SMEM_SZ);
    cudaFuncSetAttribute(stage2, cudaFuncAttributeMaxDynamicSharedMemorySize, SMEM_SZ);

    init_mats<<<128, 256>>>();
    stage1<<<dim3(32, 16, 8), 512, SMEM_SZ>>>(X);
    stage2<<<dim3(109, 16), 512, SMEM_SZ>>>(out);
}

// round 8
// speedup vs baseline: 4.4193x; 2.1140x over previous
#include <cuda_runtime.h>
#include <cuda_fp16.h>
#include <math.h>

// Spectral_Pool: out = P X P^T - Q X Q^T  (P+iQ = Dirichlet DFT crop matrix)
// Single-product fp16 GEMMs on mma.sync.m16n8k16 (f32 accumulate).
//
// Stage1 (per b, w-blk, c-blk, z):  T_z[p, c, w] = sum_h A1_z[p,h] X[b,h,w,c]
//   z=0: P rows (217 valid, padded 256), z=1: Q rows.  T fp16 [b][z*224+p][c][w].
// Stage2 (per b, row-pair mi): out[mi, mo, c] = sum_{j,w} A2[mo, j*256+w] T[b, j*224+mi, c, w]
//   A2[mo][j*256+w] = j ? -Q[mo][w] : P[mo][w].

#define PI_D 3.14159265358979323846

// ---------------- device globals ----------------
// fragment-ordered fp16 A matrices: [blk][mt 16][lane 32][8]
__device__ __align__(16) __half g_A1f[32 * 16 * 32 * 8];   // 256 KB, blk = k16*2+z
__device__ __align__(16) __half g_A2f[32 * 16 * 32 * 8];   // 256 KB, blk = k16
// T intermediate fp16: [b 16][row 448][c 64][w 256]
__device__ __align__(16) __half g_T[(size_t)16 * 448 * 64 * 256];   // 224 MB

// ---------------- helpers ----------------
__device__ __forceinline__ unsigned su32(const void* p) {
    unsigned r;
    asm("{ .reg .u64 t; cvta.to.shared.u64 t, %1; cvt.u32.u64 %0, t; }" : "=r"(r) : "l"(p));
    return r;
}
__device__ __forceinline__ void cp16(unsigned s, const void* g) {
    asm volatile("cp.async.cg.shared.global [%0],[%1],16;" :: "r"(s), "l"(g));
}
__device__ __forceinline__ void cp_commit() { asm volatile("cp.async.commit_group;"); }
__device__ __forceinline__ void cp_wait0() { asm volatile("cp.async.wait_group 0;"); }

__device__ __forceinline__ void mma_f16(float* d, const unsigned* a, const unsigned* b) {
    asm volatile(
        "mma.sync.aligned.m16n8k16.row.col.f32.f16.f16.f32 "
        "{%0,%1,%2,%3},{%4,%5,%6,%7},{%8,%9},{%0,%1,%2,%3};"
        : "+f"(d[0]), "+f"(d[1]), "+f"(d[2]), "+f"(d[3])
        : "r"(a[0]), "r"(a[1]), "r"(a[2]), "r"(a[3]), "r"(b[0]), "r"(b[1]));
}

// smem layout (bytes), both stages:
//   A bufs: [0,16384), [16384,32768)   (one K=32 chunk of fragments, fp16)
//   B bufs: 32768 + buf*10240          (128 rows x 80 B; 64 B data + pad,
//                                       16B-aligned rows, stride 20 banks)
#define SM_A(buf) ((buf) * 16384)
#define SM_B(buf) (32768 + (buf) * 10240)
#define BROW 80
#define SMEM_SZ 53248

// ---------------- init: build fragment-ordered fp16 A1/A2 ----------------
__device__ __forceinline__ double dirichlet_d(long long p) {
    if (p == 0) return 217.0;
    return sin(PI_D * (double)p / 256.0) / sin(PI_D * (double)p / 55552.0);
}

__global__ void init_mats() {
    int t = blockIdx.x * blockDim.x + threadIdx.x;
    if (t >= 32768) return;
    __half v8[8];

    if (t < 16384) {
        int lane = t & 31, mt = (t >> 5) & 15, zz = (t >> 9) & 1, k16 = t >> 10;
        int gid = lane >> 2, tig = lane & 3;
#pragma unroll
        for (int r = 0; r < 8; r++) {
            int row = gid + ((r >> 1) & 1) * 8;
            int col = tig * 2 + (r & 1) + ((r >> 2) & 1) * 8;
            int ml = mt * 16 + row;
            int h = k16 * 16 + col;
            double v = 0.0;
            if (ml < 217) {
                double d = dirichlet_d(256LL * ml - 217LL * h);
                double ph = 2.0 * PI_D * (double)h / 256.0;
                v = (d / 217.0) * (zz ? sin(ph) : cos(ph));
            }
            v8[r] = __float2half_rn((float)v);
        }
        size_t base = ((size_t)((k16 * 2 + zz) * 16 + mt)) * 256 + lane * 8;
        *reinterpret_cast<uint4*>(&g_A1f[base]) = *reinterpret_cast<uint4*>(v8);
    } else {
        int t2 = t - 16384;
        int lane = t2 & 31, mt = (t2 >> 5) & 15, k16 = t2 >> 9;
        int gid = lane >> 2, tig = lane & 3;
#pragma unroll
        for (int r = 0; r < 8; r++) {
            int row = gid + ((r >> 1) & 1) * 8;
            int col = tig * 2 + (r & 1) + ((r >> 2) & 1) * 8;
            int mo = mt * 16 + row;
            int k = k16 * 16 + col;
            double v = 0.0;
            if (mo < 217) {
                int j = k >> 8, w = k & 255;
                double d = dirichlet_d(256LL * mo - 217LL * w);
                double ph = 2.0 * PI_D * (double)w / 256.0;
                v = (d / 217.0) * (j ? -sin(ph) : cos(ph));
            }
            v8[r] = __float2half_rn((float)v);
        }
        size_t base = ((size_t)(k16 * 16 + mt)) * 256 + lane * 8;
        *reinterpret_cast<uint4*>(&g_A2f[base]) = *reinterpret_cast<uint4*>(v8);
    }
}

// ---------------- mma chunk (k=32, single product) ----------------
// warp tile M64 x N32; acc[4 mt][4 nt][4]
__device__ __forceinline__ void mma_chunk(unsigned char* sm, int buf, int wm, int wn,
                                          int lane, float acc[4][4][4]) {
    int gid = lane >> 2, tig = lane & 3;
#pragma unroll
    for (int kk = 0; kk < 2; kk++) {
        unsigned bh[4][2];
#pragma unroll
        for (int nt = 0; nt < 4; nt++) {
            int n = wn * 32 + nt * 8 + gid;
            int base = SM_B(buf) + n * BROW + kk * 32 + tig * 4;
            bh[nt][0] = *reinterpret_cast<const unsigned*>(sm + base);
            bh[nt][1] = *reinterpret_cast<const unsigned*>(sm + base + 16);
        }
        unsigned a[4][4];
#pragma unroll
        for (int mt = 0; mt < 4; mt++) {
            const uint4 v = *reinterpret_cast<const uint4*>(
                sm + SM_A(buf) + ((kk * 16 + wm * 4 + mt) * 32 + lane) * 16);
            a[mt][0] = v.x; a[mt][1] = v.y; a[mt][2] = v.z; a[mt][3] = v.w;
        }
#pragma unroll
        for (int mt = 0; mt < 4; mt++)
#pragma unroll
            for (int nt = 0; nt < 4; nt++) mma_f16(acc[mt][nt], a[mt], bh[nt]);
    }
}

// ---------------- stage 1 ----------------
// grid (32 wblk, 16 b, 8 = cblk*2+z), 512 threads. M=256, N=128 (8w x 16c), K=256.
__global__ __launch_bounds__(512, 1) void stage1(const float* __restrict__ X) {
    extern __shared__ unsigned char sm[];
    const int tid = threadIdx.x, wid = tid >> 5, lane = tid & 31;
    const int wm = wid & 3, wn = wid >> 2;
    const int gid = lane >> 2, tig = lane & 3;
    const int b = blockIdx.y, w0 = blockIdx.x * 8;
    const int zz = blockIdx.z & 1, c0 = (blockIdx.z >> 1) * 16;

    float acc[4][4][4];
#pragma unroll
    for (int i = 0; i < 4; i++)
#pragma unroll
        for (int j = 0; j < 4; j++)
#pragma unroll
            for (int k = 0; k < 4; k++) acc[i][j][k] = 0.f;

    float4 xr[2];

#define LOADX(CH)                                                                      \
    _Pragma("unroll") for (int p = 0; p < 2; p++) {                                    \
        int i = tid + p * 512;                                                         \
        int kk = i >> 5, rr = i & 31, wl = rr >> 2, c4 = rr & 3;                       \
        xr[p] = *reinterpret_cast<const float4*>(                                      \
            X + ((size_t)((b * 256 + (CH) * 32 + kk) * 256) + (w0 + wl)) * 64 +        \
            c0 + c4 * 4);                                                              \
    }

#define STOREB(BUF)                                                                    \
    _Pragma("unroll") for (int p = 0; p < 2; p++) {                                    \
        int i = tid + p * 512;                                                         \
        int kk = i >> 5, rr = i & 31, wl = rr >> 2, c4 = rr & 3;                       \
        float v[4] = {xr[p].x, xr[p].y, xr[p].z, xr[p].w};                             \
        _Pragma("unroll") for (int e = 0; e < 4; e++) {                                \
            int n = (c4 * 4 + e) * 8 + wl;                                             \
            *reinterpret_cast<__half*>(sm + SM_B(BUF) + n * BROW + kk * 2) =           \
                __float2half_rn(v[e]);                                                 \
        }                                                                              \
    }

#define CPA1(CH, BUF)                                                                  \
    _Pragma("unroll") for (int q = 0; q < 2; q++) {                                    \
        int i = tid + q * 512;                                                         \
        int kk2 = i >> 9, o = i & 511;                                                 \
        cp16(su32(sm + SM_A(BUF) + kk2 * 8192 + o * 16),                               \
             reinterpret_cast<const char*>(g_A1f) +                                    \
                 (size_t)(((CH) * 2 + kk2) * 2 + zz) * 8192 + o * 16);                 \
    }

    LOADX(0);
    STOREB(0);
    CPA1(0, 0);
    cp_commit();
    LOADX(1);

    for (int ch = 0; ch < 8; ch++) {
        cp_wait0();
        __syncthreads();    // A(ch)/B(ch) ready; all warps past mma(ch-1)
        if (ch < 7) {
            STOREB((ch + 1) & 1);
            CPA1(ch + 1, (ch + 1) & 1);
            cp_commit();
            if (ch < 6) LOADX(ch + 2);
        }
        mma_chunk(sm, ch & 1, wm, wn, lane, acc);
    }
#undef LOADX
#undef STOREB
#undef CPA1

    // epilogue: acc -> fp16 T[b][zz*224+row][c][w] (half2 packed w-pairs)
#pragma unroll
    for (int mt = 0; mt < 4; mt++) {
#pragma unroll
        for (int nt = 0; nt < 4; nt++) {
            int n0 = wn * 32 + nt * 8 + 2 * tig;
            int w = w0 + (n0 & 7);
            int cc = c0 + (n0 >> 3);
            int lr0 = wm * 64 + mt * 16 + gid;
#pragma unroll
            for (int half = 0; half < 2; half++) {
                int lr = lr0 + half * 8;
                if (lr < 224) {
                    __half2 hv = __floats2half2_rn(acc[mt][nt][half * 2 + 0],
                                                   acc[mt][nt][half * 2 + 1]);
                    size_t elem = ((size_t)((b * 448 + zz * 224 + lr) * 64 + cc)) * 256 + w;
                    *reinterpret_cast<__half2*>(&g_T[elem]) = hv;
                }
            }
        }
    }
}

// ---------------- stage 2 ----------------
// grid (109 mi-pairs, 16 b), 512 threads. M=256 (mo), N=128 (2 mi x 64 c), K=512.
__device__ __forceinline__ void s2_fill(unsigned char* sm, int buf, int ch, int tid,
                                        int b, int m2t) {
    // A: 16KB fragment chunk
#pragma unroll
    for (int q = 0; q < 2; q++) {
        int i = tid + q * 512;
        int kk2 = i >> 9, o = i & 511;
        cp16(su32(sm + SM_A(buf) + kk2 * 8192 + o * 16),
             reinterpret_cast<const char*>(g_A2f) + (size_t)(ch * 2 + kk2) * 8192 + o * 16);
    }
    // B: 8KB from T (fp16, w-contiguous): 128 rows x 64B (4 x 16B each)
    const int j = ch >> 3, w0 = (ch & 7) * 32;
    {
        int n = tid >> 2, qq = tid & 3;
        int m2l = n >> 6, cc = n & 63;
        size_t elem = ((size_t)((b * 448 + j * 224 + m2t * 2 + m2l) * 64 + cc)) * 256 + w0;
        cp16(su32(sm + SM_B(buf) + n * BROW + qq * 16),
             reinterpret_cast<const char*>(g_T) + elem * 2 + qq * 16);
    }
    cp_commit();
}

__global__ __launch_bounds__(512, 1) void stage2(float* __restrict__ out) {
    extern __shared__ unsigned char sm[];
    const int tid = threadIdx.x, wid = tid >> 5, lane = tid & 31;
    const int wm = wid & 3, wn = wid >> 2;
    const int gid = lane >> 2, tig = lane & 3;
    const int b = blockIdx.y, m2t = blockIdx.x;

    float acc[4][4][4];
#pragma unroll
    for (int i = 0; i < 4; i++)
#pragma unroll
        for (int j = 0; j < 4; j++)
#pragma unroll
            for (int k = 0; k < 4; k++) acc[i][j][k] = 0.f;

    s2_fill(sm, 0, 0, tid, b, m2t);
    for (int ch = 0; ch < 16; ch++) {
        cp_wait0();          // fill(ch) complete
        __syncthreads();     // all warps past mma(ch-1): buf^1 safe to overwrite
        if (ch < 15) s2_fill(sm, (ch + 1) & 1, ch + 1, tid, b, m2t);
        mma_chunk(sm, ch & 1, wm, wn, lane, acc);
    }

    // epilogue: out[b][mi][mo][c]
#pragma unroll
    for (int mt = 0; mt < 4; mt++) {
#pragma unroll
        for (int nt = 0; nt < 4; nt++) {
            int n0 = wn * 32 + nt * 8 + 2 * tig;
            int mi = m2t * 2 + (n0 >> 6);
            int cc = n0 & 63;
            int mo0 = wm * 64 + mt * 16 + gid;
            if (mi < 217) {
#pragma unroll
                for (int half = 0; half < 2; half++) {
                    int mo = mo0 + half * 8;
                    if (mo < 217) {
                        size_t e = ((size_t)((b * 217 + mi) * 217 + mo)) * 64 + cc;
                        float2 v = make_float2(acc[mt][nt][half * 2 + 0],
                                               acc[mt][nt][half * 2 + 1]);
                        *reinterpret_cast<float2*>(out + e) = v;
                    }
                }
            }
        }
    }
}

// ---------------- launch ----------------
extern "C" void kernel_launch(void* const* d_in, const int* in_sizes, int n_in,
                              void* d_out, int out_size) {
    const float* X = (const float*)d_in[0];
    float* out = (float*)d_out;

    cudaFuncSetAttribute(stage1, cudaFuncAttributeMaxDynamicSharedMemorySize, SMEM_SZ);
    cudaFuncSetAttribute(stage2, cudaFuncAttributeMaxDynamicSharedMemorySize, SMEM_SZ);

    init_mats<<<128, 256>>>();
    stage1<<<dim3(32, 16, 8), 512, SMEM_SZ>>>(X);
    stage2<<<dim3(109, 16), 512, SMEM_SZ>>>(out);
}